// round 5
// baseline (speedup 1.0000x reference)
#include <cuda_runtime.h>
#include <cuda_bf16.h>
#include <cstdint>

#define B_ 2
#define H_ 12
#define S_ 256
#define E_ 64
#define D_ 768
#define L_ 25
#define RS (S_ * D_)      // rel sq-stride (floats)
#define NCHUNK 48         // k16 chunks

typedef unsigned long long u64;
typedef unsigned int u32;

// ---- smem layout (float offsets) ----
#define OFF_WS   0         // W packed frags: 2 dtypes x 48 x 32 x 8 u32 = 24576
#define OFF_PS   24576     // 12 x 256
#define OFF_VS   27648     // 768
#define OFF_CVS  28416     // 25*12 = 300
#define OFF_BIAS 28716     // 32
#define SMEM_FLOATS 28748  // 114992 bytes

#define WPN (48 * 32 * 8)  // u32 per dtype

__device__ float g_pt[B_ * H_ * S_ * S_];
__device__ u32   g_wp[2 * WPN];

__global__ void transpose_p_kernel(const float* __restrict__ p) {
    __shared__ float tile[32][33];
    int bh = blockIdx.z, x0 = blockIdx.x * 32, y0 = blockIdx.y * 32;
    int tx = threadIdx.x, ty = threadIdx.y;
    const float* src = p + (size_t)bh * (S_ * S_);
#pragma unroll
    for (int j = 0; j < 32; j += 8)
        tile[ty + j][tx] = src[(size_t)(y0 + ty + j) * S_ + (x0 + tx)];
    __syncthreads();
    float* dst = g_pt + (size_t)bh * (S_ * S_);
#pragma unroll
    for (int j = 0; j < 32; j += 8)
        dst[(size_t)(x0 + ty + j) * S_ + (y0 + tx)] = tile[tx][ty + j];
}

// split two f32 into bf16x2 hi + bf16x2 lo (x0 -> low 16 bits = first k)
__device__ __forceinline__ void split_pair(float x0, float x1, u32& hi2, u32& lo2) {
    asm("cvt.rn.bf16x2.f32 %0, %1, %2;" : "=r"(hi2) : "f"(x1), "f"(x0));
    float h0 = __uint_as_float(hi2 << 16);
    float h1 = __uint_as_float(hi2 & 0xffff0000u);
    asm("cvt.rn.bf16x2.f32 %0, %1, %2;" : "=r"(lo2) : "f"(x1 - h1), "f"(x0 - h0));
}

// Pack W into mma B-fragment layout: g_wp[d][s][n][tg][j], j=0:k=16s+2tg, j=1:+8
__global__ void pack_w_kernel(const float* __restrict__ W) {
    int t = blockIdx.x * 256 + threadIdx.x;       // 0..6143
    if (t >= 48 * 32 * 4) return;
    int s = t >> 7, r = t & 127;
    int n = r >> 2, tg = r & 3;
#pragma unroll
    for (int j = 0; j < 2; ++j) {
        int k = 16 * s + 2 * tg + 8 * j;
        float w0 = (n < L_) ? W[n * D_ + k] : 0.0f;
        float w1 = (n < L_) ? W[n * D_ + k + 1] : 0.0f;
        u32 hi2, lo2;
        split_pair(w0, w1, hi2, lo2);
        int idx = (s * 32 + n) * 8 + tg * 2 + j;
        g_wp[idx] = hi2;
        g_wp[WPN + idx] = lo2;
    }
}

__device__ __forceinline__ void mma_bf16(float* c, const u32* a, u32 b0, u32 b1) {
    asm volatile(
        "mma.sync.aligned.m16n8k16.row.col.f32.bf16.bf16.f32 "
        "{%0,%1,%2,%3}, {%4,%5,%6,%7}, {%8,%9}, {%0,%1,%2,%3};"
        : "+f"(c[0]), "+f"(c[1]), "+f"(c[2]), "+f"(c[3])
        : "r"(a[0]), "r"(a[1]), "r"(a[2]), "r"(a[3]), "r"(b0), "r"(b1));
}

__global__ void __launch_bounds__(256, 1) mhs_mma_kernel(
    const float* __restrict__ v,     // [B,H,S,E]
    const float* __restrict__ rel,   // [B,S,S,768]
    const float* __restrict__ W,     // [25,768] fp32
    const float* __restrict__ bias,  // [25]
    float* __restrict__ out)         // [B,S,25,S]
{
    extern __shared__ float smem[];
    const int tid  = threadIdx.x;
    const int w    = tid >> 5;           // warp 0..7, owns sq rows 32w..32w+31
    const int lane = tid & 31;
    const int g    = lane >> 2;          // groupID
    const int tg   = lane & 3;           // thread-in-group

    const int blk = blockIdx.x;
    const int b   = blk >> 8;
    const int sk  = blk & 255;

    float* p_s    = smem + OFF_PS;
    float* v_s    = smem + OFF_VS;
    float* cv_s   = smem + OFF_CVS;
    float* bias_s = smem + OFF_BIAS;
    const u32* wsh = (const u32*)smem;                 // hi frags
    const u32* wsl = wsh + WPN;                        // lo frags

    const float* relb = rel + (size_t)b * S_ * RS + (size_t)sk * D_;
    const float* myrel = relb + (size_t)(32 * w) * RS;

    // fragment row pointers (col base added per chunk)
    const float* r0 = myrel + (size_t)(g     ) * RS + 2 * tg;
    const float* r1 = myrel + (size_t)(g +  8) * RS + 2 * tg;
    const float* r2 = myrel + (size_t)(g + 16) * RS + 2 * tg;
    const float* r3 = myrel + (size_t)(g + 24) * RS + 2 * tg;

    // ---- stage p_s, v_s, bias ----
    for (int i = tid; i < H_ * S_; i += 256) {
        int h = i >> 8, sq = i & 255;
        p_s[i] = g_pt[(((size_t)b * H_ + h) * S_ + sk) * S_ + sq];
    }
    for (int i = tid; i < D_; i += 256) {
        int h = i >> 6, e = i & 63;
        v_s[i] = v[(((size_t)b * H_ + h) * S_ + sk) * E_ + e];
    }
    if (tid < L_) bias_s[tid] = bias[tid];

    // ---- stage packed W (96KB from L2) ----
    {
        const uint4* src = (const uint4*)g_wp;
        uint4* dst = (uint4*)smem;
        for (int i = tid; i < 2 * WPN / 4; i += 256) dst[i] = src[i];
    }
    __syncthreads();

    // ---- cv[l][h] = sum_e W[l, 64h+e] * v[h,e] ----
    for (int task = tid; task < L_ * H_; task += 256) {
        int l = task / H_, h = task - l * H_;
        const float4* wr = (const float4*)(W + l * D_ + h * 64);
        const float4* vr = (const float4*)(v_s + h * 64);
        float s = 0.f;
#pragma unroll
        for (int e = 0; e < 16; ++e) {
            float4 a = wr[e], c = vr[e];
            s += a.x * c.x + a.y * c.y + a.z * c.z + a.w * c.w;
        }
        cv_s[task] = s;
    }
    __syncthreads();

    // ---- accumulators ----
    float acc[2][4][4];
#pragma unroll
    for (int m = 0; m < 2; ++m)
#pragma unroll
        for (int nt = 0; nt < 4; ++nt)
#pragma unroll
            for (int q = 0; q < 4; ++q) acc[m][nt][q] = 0.f;

    // ---- register A buffers: 4 chunks deep ----
    float2 bufs[4][8];

#define LDCHUNK(cc, dst)                                                \
    do {                                                                \
        const int _col = 16 * (cc);                                     \
        (dst)[0] = __ldg((const float2*)(r0 + _col));                   \
        (dst)[1] = __ldg((const float2*)(r1 + _col));                   \
        (dst)[2] = __ldg((const float2*)(r0 + _col + 8));               \
        (dst)[3] = __ldg((const float2*)(r1 + _col + 8));               \
        (dst)[4] = __ldg((const float2*)(r2 + _col));                   \
        (dst)[5] = __ldg((const float2*)(r3 + _col));                   \
        (dst)[6] = __ldg((const float2*)(r2 + _col + 8));               \
        (dst)[7] = __ldg((const float2*)(r3 + _col + 8));               \
    } while (0)

    LDCHUNK(0, bufs[0]);
    LDCHUNK(1, bufs[1]);
    LDCHUNK(2, bufs[2]);

    float pv[4] = {0.f, 0.f, 0.f, 0.f};   // pA0, pB0, pA1, pB1

#pragma unroll 1
    for (int c = 0; c < NCHUNK; c += 4) {
#pragma unroll
        for (int u = 0; u < 4; ++u) {
            const int cc = c + u;

            if (u == 0) {
                const int h = cc >> 2;
                const float* pb = p_s + h * 256 + 32 * w;
                pv[0] = pb[g];
                pv[1] = pb[g + 8];
                pv[2] = pb[g + 16];
                pv[3] = pb[g + 24];
            }

            // convert consumed buffer -> bf16 hi/lo fragments
            u32 ah[2][4], al[2][4];
            {
                const float2* d = bufs[u];
#pragma unroll
                for (int m = 0; m < 2; ++m) {
                    const float pA = pv[2 * m];
                    const float pB = pv[2 * m + 1];
                    const float2 f0 = d[4 * m + 0];
                    const float2 f1 = d[4 * m + 1];
                    const float2 f2 = d[4 * m + 2];
                    const float2 f3 = d[4 * m + 3];
                    split_pair(f0.x * pA, f0.y * pA, ah[m][0], al[m][0]);
                    split_pair(f1.x * pB, f1.y * pB, ah[m][1], al[m][1]);
                    split_pair(f2.x * pA, f2.y * pA, ah[m][2], al[m][2]);
                    split_pair(f3.x * pB, f3.y * pB, ah[m][3], al[m][3]);
                }
            }

            // prefetch chunk cc+3 into the buffer consumed last iteration
            if (cc + 3 < NCHUNK) {
                LDCHUNK(cc + 3, bufs[(u + 3) & 3]);
            }

            // MMAs: 4 ntiles x (2 mtiles x 3 split terms)
#pragma unroll
            for (int nt = 0; nt < 4; ++nt) {
                const int bi = (cc * 32 + nt * 8 + g) * 8 + tg * 2;
                u64 bhp = *(const u64*)(wsh + bi);
                u64 blp = *(const u64*)(wsl + bi);
                u32 bh0 = (u32)bhp, bh1 = (u32)(bhp >> 32);
                u32 bl0 = (u32)blp, bl1 = (u32)(blp >> 32);
#pragma unroll
                for (int m = 0; m < 2; ++m) {
                    mma_bf16(acc[m][nt], ah[m], bh0, bh1);
                    mma_bf16(acc[m][nt], al[m], bh0, bh1);
                    mma_bf16(acc[m][nt], ah[m], bl0, bl1);
                }
            }
        }
    }
#undef LDCHUNK

    // ---- epilogue: bias + v-correction + store ----
    float* ob = out + ((size_t)(b * S_ + sk) * L_) * S_;
#pragma unroll
    for (int m = 0; m < 2; ++m) {
#pragma unroll
        for (int i = 0; i < 2; ++i) {
            const int row = 32 * w + 16 * m + g + 8 * i;
            float pr[H_];
#pragma unroll
            for (int h = 0; h < H_; ++h) pr[h] = p_s[h * 256 + row];
#pragma unroll
            for (int nt = 0; nt < 4; ++nt) {
#pragma unroll
                for (int j = 0; j < 2; ++j) {
                    const int l = 8 * nt + 2 * tg + j;
                    if (l < L_) {
                        float val = acc[m][nt][2 * i + j] + bias_s[l];
#pragma unroll
                        for (int h = 0; h < H_; ++h)
                            val += pr[h] * cv_s[l * H_ + h];
                        ob[(size_t)l * S_ + row] = val;
                    }
                }
            }
        }
    }
}

extern "C" void kernel_launch(void* const* d_in, const int* in_sizes, int n_in,
                              void* d_out, int out_size) {
    const float* p    = (const float*)d_in[0];
    const float* v    = (const float*)d_in[1];
    const float* rel  = (const float*)d_in[2];
    const float* W    = (const float*)d_in[3];
    const float* bias = (const float*)d_in[4];
    float* out = (float*)d_out;

    dim3 gt(S_ / 32, S_ / 32, B_ * H_);
    transpose_p_kernel<<<gt, dim3(32, 8)>>>(p);
    pack_w_kernel<<<24, 256>>>(W);

    const int smem_bytes = SMEM_FLOATS * (int)sizeof(float);  // 114992
    cudaFuncSetAttribute(mhs_mma_kernel,
                         cudaFuncAttributeMaxDynamicSharedMemorySize, smem_bytes);
    mhs_mma_kernel<<<B_ * S_, 256, smem_bytes>>>(v, rel, W, bias, out);
}

// round 6
// speedup vs baseline: 1.0328x; 1.0328x over previous
#include <cuda_runtime.h>
#include <cuda_bf16.h>
#include <cstdint>

#define B_ 2
#define H_ 12
#define S_ 256
#define E_ 64
#define D_ 768
#define L_ 25
#define RS (S_ * D_)      // rel sq-stride (floats)
#define NCHUNK 48         // k16 chunks

typedef unsigned long long u64;
typedef unsigned int u32;

// ---- smem layout (float offsets) ----
#define OFF_WS   0         // W packed frags: 2 dtypes x 48 x 32 x 8 u32 = 24576
#define OFF_RAW  24576     // 8 warps x 4 bufs x 32 rows x 24 floats = 24576
#define OFF_PS   49152     // 12 x 256
#define OFF_VS   52224     // 768
#define OFF_CVS  52992     // 25*12 = 300
#define OFF_BIAS 53296     // 32
#define SMEM_FLOATS 53328  // 213312 bytes

#define WPN (48 * 32 * 8)  // u32 per dtype

__device__ float g_pt[B_ * H_ * S_ * S_];
__device__ u32   g_wp[2 * WPN];

__global__ void transpose_p_kernel(const float* __restrict__ p) {
    __shared__ float tile[32][33];
    int bh = blockIdx.z, x0 = blockIdx.x * 32, y0 = blockIdx.y * 32;
    int tx = threadIdx.x, ty = threadIdx.y;
    const float* src = p + (size_t)bh * (S_ * S_);
#pragma unroll
    for (int j = 0; j < 32; j += 8)
        tile[ty + j][tx] = src[(size_t)(y0 + ty + j) * S_ + (x0 + tx)];
    __syncthreads();
    float* dst = g_pt + (size_t)bh * (S_ * S_);
#pragma unroll
    for (int j = 0; j < 32; j += 8)
        dst[(size_t)(x0 + ty + j) * S_ + (y0 + tx)] = tile[tx][ty + j];
}

// split two f32 into bf16x2 hi + bf16x2 lo (x0 -> low 16 bits = first k)
__device__ __forceinline__ void split_pair(float x0, float x1, u32& hi2, u32& lo2) {
    asm("cvt.rn.bf16x2.f32 %0, %1, %2;" : "=r"(hi2) : "f"(x1), "f"(x0));
    float h0 = __uint_as_float(hi2 << 16);
    float h1 = __uint_as_float(hi2 & 0xffff0000u);
    asm("cvt.rn.bf16x2.f32 %0, %1, %2;" : "=r"(lo2) : "f"(x1 - h1), "f"(x0 - h0));
}

// Pack W into mma B-fragment layout: g_wp[d][s][n][tg][j], j=0:k=16s+2tg, j=1:+8
__global__ void pack_w_kernel(const float* __restrict__ W) {
    int t = blockIdx.x * 256 + threadIdx.x;       // 0..6143
    if (t >= 48 * 32 * 4) return;
    int s = t >> 7, r = t & 127;
    int n = r >> 2, tg = r & 3;
#pragma unroll
    for (int j = 0; j < 2; ++j) {
        int k = 16 * s + 2 * tg + 8 * j;
        float w0 = (n < L_) ? W[n * D_ + k] : 0.0f;
        float w1 = (n < L_) ? W[n * D_ + k + 1] : 0.0f;
        u32 hi2, lo2;
        split_pair(w0, w1, hi2, lo2);
        int idx = (s * 32 + n) * 8 + tg * 2 + j;
        g_wp[idx] = hi2;
        g_wp[WPN + idx] = lo2;
    }
}

__device__ __forceinline__ void cpasync16(u32 dst, const float* src) {
    asm volatile("cp.async.cg.shared.global [%0], [%1], 16;\n" :: "r"(dst), "l"(src));
}
__device__ __forceinline__ void cp_commit() {
    asm volatile("cp.async.commit_group;\n" ::: "memory");
}
__device__ __forceinline__ void cp_wait2() {
    asm volatile("cp.async.wait_group 2;\n" ::: "memory");
}
__device__ __forceinline__ u32 smem_u32(const void* p) {
    u32 r;
    asm("{ .reg .u64 t; cvta.to.shared.u64 t, %1; cvt.u32.u64 %0, t; }" : "=r"(r) : "l"(p));
    return r;
}
__device__ __forceinline__ void mma_bf16(float* c, const u32* a, u32 b0, u32 b1) {
    asm volatile(
        "mma.sync.aligned.m16n8k16.row.col.f32.bf16.bf16.f32 "
        "{%0,%1,%2,%3}, {%4,%5,%6,%7}, {%8,%9}, {%0,%1,%2,%3};"
        : "+f"(c[0]), "+f"(c[1]), "+f"(c[2]), "+f"(c[3])
        : "r"(a[0]), "r"(a[1]), "r"(a[2]), "r"(a[3]), "r"(b0), "r"(b1));
}

__global__ void __launch_bounds__(256, 1) mhs_mma_kernel(
    const float* __restrict__ v,     // [B,H,S,E]
    const float* __restrict__ rel,   // [B,S,S,768]
    const float* __restrict__ W,     // [25,768] fp32
    const float* __restrict__ bias,  // [25]
    float* __restrict__ out)         // [B,S,25,S]
{
    extern __shared__ float smem[];
    const int tid  = threadIdx.x;
    const int w    = tid >> 5;           // warp 0..7, owns sq rows 32w..32w+31
    const int lane = tid & 31;
    const int g    = lane >> 2;          // groupID
    const int tg   = lane & 3;           // thread-in-group

    const int blk = blockIdx.x;
    const int b   = blk >> 8;
    const int sk  = blk & 255;

    float* p_s    = smem + OFF_PS;
    float* v_s    = smem + OFF_VS;
    float* cv_s   = smem + OFF_CVS;
    float* bias_s = smem + OFF_BIAS;
    float* rawb   = smem + OFF_RAW + w * (4 * 768);   // 4 bufs x 768 floats
    const u32 raw_su = smem_u32(rawb);
    const u32* wsh = (const u32*)smem;                 // hi frags
    const u32* wsl = wsh + WPN;                        // lo frags

    const float* relb = rel + (size_t)b * S_ * RS + (size_t)sk * D_;
    const float* myrel = relb + (size_t)(32 * w) * RS;

    // ---- prefetch chunks 0..2 (per-warp, 4 cp.async.16 per lane per chunk) ----
#pragma unroll
    for (int c = 0; c < 3; ++c) {
#pragma unroll
        for (int i = 0; i < 4; ++i) {
            int r = g + 8 * i;
            cpasync16(raw_su + (u32)(c * 3072 + r * 96 + tg * 16),
                      myrel + (size_t)r * RS + 16 * c + tg * 4);
        }
        cp_commit();
    }

    // ---- stage p_s, v_s, bias ----
    for (int i = tid; i < H_ * S_; i += 256) {
        int h = i >> 8, sq = i & 255;
        p_s[i] = g_pt[(((size_t)b * H_ + h) * S_ + sk) * S_ + sq];
    }
    for (int i = tid; i < D_; i += 256) {
        int h = i >> 6, e = i & 63;
        v_s[i] = v[(((size_t)b * H_ + h) * S_ + sk) * E_ + e];
    }
    if (tid < L_) bias_s[tid] = bias[tid];

    // ---- stage packed W (96KB from L2) ----
    {
        const uint4* src = (const uint4*)g_wp;
        uint4* dst = (uint4*)smem;
        for (int i = tid; i < 2 * WPN / 4; i += 256) dst[i] = src[i];
    }
    __syncthreads();

    // ---- cv[l][h] = sum_e W[l, 64h+e] * v[h,e] ----
    for (int task = tid; task < L_ * H_; task += 256) {
        int l = task / H_, h = task - l * H_;
        const float4* wr = (const float4*)(W + l * D_ + h * 64);
        const float4* vr = (const float4*)(v_s + h * 64);
        float s = 0.f;
#pragma unroll
        for (int e = 0; e < 16; ++e) {
            float4 a = wr[e], c = vr[e];
            s += a.x * c.x + a.y * c.y + a.z * c.z + a.w * c.w;
        }
        cv_s[task] = s;
    }
    __syncthreads();

    // ---- accumulators ----
    float acc[2][4][4];
#pragma unroll
    for (int m = 0; m < 2; ++m)
#pragma unroll
        for (int nt = 0; nt < 4; ++nt)
#pragma unroll
            for (int q = 0; q < 4; ++q) acc[m][nt][q] = 0.f;

    // ---- double-buffered converted fragments ----
    u32 ah[2][2][4], al[2][2][4];   // [parity][mtile][frag]
    float pv[4];

    const float* pbase = p_s + 32 * w;

    // convert chunk `cc` (resident in raw buf cc&3) into parity slot `pp`
#define CONVERT(cc, pp)                                                   \
    do {                                                                  \
        const float* rp_ = rawb + ((cc) & 3) * 768;                       \
        _Pragma("unroll")                                                 \
        for (int m_ = 0; m_ < 2; ++m_) {                                  \
            const float* rr_ = rp_ + (16 * m_) * 24;                      \
            const float pA_ = pv[2 * m_];                                 \
            const float pB_ = pv[2 * m_ + 1];                             \
            float2 f0 = *(const float2*)(rr_ + g * 24 + 2 * tg);          \
            float2 f1 = *(const float2*)(rr_ + (g + 8) * 24 + 2 * tg);    \
            float2 f2 = *(const float2*)(rr_ + g * 24 + 2 * tg + 8);      \
            float2 f3 = *(const float2*)(rr_ + (g + 8) * 24 + 2 * tg + 8);\
            split_pair(f0.x * pA_, f0.y * pA_, ah[pp][m_][0], al[pp][m_][0]); \
            split_pair(f1.x * pB_, f1.y * pB_, ah[pp][m_][1], al[pp][m_][1]); \
            split_pair(f2.x * pA_, f2.y * pA_, ah[pp][m_][2], al[pp][m_][2]); \
            split_pair(f3.x * pB_, f3.y * pB_, ah[pp][m_][3], al[pp][m_][3]); \
        }                                                                 \
    } while (0)

#define LOADPV(hh)                                                        \
    do {                                                                  \
        const float* pb_ = pbase + (hh) * 256;                            \
        pv[0] = pb_[g]; pv[1] = pb_[g + 8];                               \
        pv[2] = pb_[g + 16]; pv[3] = pb_[g + 24];                         \
    } while (0)

    // prologue: chunk 0 resident -> convert into parity 0
    cp_wait2();
    LOADPV(0);
    CONVERT(0, 0);

#pragma unroll 1
    for (int c = 0; c < NCHUNK; c += 4) {
#pragma unroll
        for (int u = 0; u < 4; ++u) {
            const int cc  = c + u;
            const int cur = u & 1;
            const int nxt = cur ^ 1;

            // 1) issue cp.async for chunk cc+3
            if (cc + 3 < NCHUNK) {
                const int c3 = cc + 3;
                const u32 du = raw_su + (u32)(((u + 3) & 3) * 3072);
#pragma unroll
                for (int i = 0; i < 4; ++i) {
                    int r = g + 8 * i;
                    cpasync16(du + (u32)(r * 96 + tg * 16),
                              myrel + (size_t)r * RS + 16 * c3 + tg * 4);
                }
            }
            cp_commit();

            // 2) MMAs for chunk cc from pre-converted fragments
#pragma unroll
            for (int nt = 0; nt < 4; ++nt) {
                const int bi = (cc * 32 + nt * 8 + g) * 8 + tg * 2;
                u64 bhp = *(const u64*)(wsh + bi);
                u64 blp = *(const u64*)(wsl + bi);
                u32 bh0 = (u32)bhp, bh1 = (u32)(bhp >> 32);
                u32 bl0 = (u32)blp, bl1 = (u32)(blp >> 32);
#pragma unroll
                for (int m = 0; m < 2; ++m) {
                    mma_bf16(acc[m][nt], ah[cur][m], bh0, bh1);
                    mma_bf16(acc[m][nt], al[cur][m], bh0, bh1);
                    mma_bf16(acc[m][nt], ah[cur][m], bl0, bl1);
                }
            }

            // 3) wait for chunk cc+1, convert into the other parity slot
            if (cc + 1 < NCHUNK) {
                cp_wait2();
                if (((cc + 1) & 3) == 0) LOADPV((cc + 1) >> 2);
                CONVERT(cc + 1, nxt);
            }
        }
    }
#undef CONVERT
#undef LOADPV

    // ---- epilogue: bias + v-correction + store ----
    float* ob = out + ((size_t)(b * S_ + sk) * L_) * S_;
#pragma unroll
    for (int m = 0; m < 2; ++m) {
#pragma unroll
        for (int i = 0; i < 2; ++i) {
            const int row = 32 * w + 16 * m + g + 8 * i;
            float pr[H_];
#pragma unroll
            for (int h = 0; h < H_; ++h) pr[h] = p_s[h * 256 + row];
#pragma unroll
            for (int nt = 0; nt < 4; ++nt) {
#pragma unroll
                for (int j = 0; j < 2; ++j) {
                    const int l = 8 * nt + 2 * tg + j;
                    if (l < L_) {
                        float val = acc[m][nt][2 * i + j] + bias_s[l];
#pragma unroll
                        for (int h = 0; h < H_; ++h)
                            val += pr[h] * cv_s[l * H_ + h];
                        ob[(size_t)l * S_ + row] = val;
                    }
                }
            }
        }
    }
}

extern "C" void kernel_launch(void* const* d_in, const int* in_sizes, int n_in,
                              void* d_out, int out_size) {
    const float* p    = (const float*)d_in[0];
    const float* v    = (const float*)d_in[1];
    const float* rel  = (const float*)d_in[2];
    const float* W    = (const float*)d_in[3];
    const float* bias = (const float*)d_in[4];
    float* out = (float*)d_out;

    dim3 gt(S_ / 32, S_ / 32, B_ * H_);
    transpose_p_kernel<<<gt, dim3(32, 8)>>>(p);
    pack_w_kernel<<<24, 256>>>(W);

    const int smem_bytes = SMEM_FLOATS * (int)sizeof(float);  // 213312
    cudaFuncSetAttribute(mhs_mma_kernel,
                         cudaFuncAttributeMaxDynamicSharedMemorySize, smem_bytes);
    mhs_mma_kernel<<<B_ * S_, 256, smem_bytes>>>(v, rel, W, bias, out);
}

// round 7
// speedup vs baseline: 1.0889x; 1.0543x over previous
#include <cuda_runtime.h>
#include <cuda_bf16.h>
#include <cstdint>

#define B_ 2
#define H_ 12
#define S_ 256
#define E_ 64
#define D_ 768
#define L_ 25
#define RS (S_ * D_)      // rel sq-stride (floats)
#define NCHUNK 48         // k16 chunks
#define RSTRIDE 28        // raw tile row stride (floats), conflict-free reads
#define RBUF (32 * RSTRIDE)  // floats per raw buffer (896)

typedef unsigned long long u64;
typedef unsigned int u32;

// ---- smem layout (float offsets) ----
#define OFF_WS   0         // W tf32 frags: 96 ksteps x 32 n x 8 = 24576 u32
#define OFF_RAW  24576     // 8 warps x 4 bufs x 896 = 28672
#define OFF_PS   53248     // 12 x 256
#define OFF_VS   56320     // 768
#define OFF_CVS  57088     // 300
#define OFF_BIAS 57388     // 32
#define SMEM_FLOATS 57420  // 229680 bytes

#define WPN 24576          // u32 in W frag region

__device__ float g_pt[B_ * H_ * S_ * S_];
__device__ u32   g_wp[WPN];

__device__ __forceinline__ u32 f2tf32(float x) {
    u32 r;
    asm("cvt.rna.tf32.f32 %0, %1;" : "=r"(r) : "f"(x));
    return r;
}

// z<24: transpose p; z==24: pack W into tf32 mma B-fragment layout
__global__ void prep_kernel(const float* __restrict__ p, const float* __restrict__ W) {
    if (blockIdx.z == 24) {
        int flat = blockIdx.y * 8 + blockIdx.x;      // 0..63
        if (flat >= 48) return;
        int t = flat * 256 + threadIdx.y * 32 + threadIdx.x;  // 0..12287
        int S = t >> 7;            // kstep 0..95
        int r = t & 127;
        int n = r >> 2, tg = r & 3;
#pragma unroll
        for (int j = 0; j < 2; ++j) {
            int k = 8 * S + tg + 4 * j;
            float wv = (n < L_) ? W[n * D_ + k] : 0.0f;
            g_wp[(S * 32 + n) * 8 + tg * 2 + j] = f2tf32(wv);
        }
        return;
    }
    __shared__ float tile[32][33];
    int bh = blockIdx.z, x0 = blockIdx.x * 32, y0 = blockIdx.y * 32;
    int tx = threadIdx.x, ty = threadIdx.y;
    const float* src = p + (size_t)bh * (S_ * S_);
#pragma unroll
    for (int j = 0; j < 32; j += 8)
        tile[ty + j][tx] = src[(size_t)(y0 + ty + j) * S_ + (x0 + tx)];
    __syncthreads();
    float* dst = g_pt + (size_t)bh * (S_ * S_);
#pragma unroll
    for (int j = 0; j < 32; j += 8)
        dst[(size_t)(x0 + ty + j) * S_ + (y0 + tx)] = tile[tx][ty + j];
}

__device__ __forceinline__ void cpasync16(u32 dst, const float* src) {
    asm volatile("cp.async.cg.shared.global [%0], [%1], 16;\n" :: "r"(dst), "l"(src));
}
__device__ __forceinline__ void cp_commit() {
    asm volatile("cp.async.commit_group;\n" ::: "memory");
}
__device__ __forceinline__ void cp_wait3() {
    asm volatile("cp.async.wait_group 3;\n" ::: "memory");
}
__device__ __forceinline__ u32 smem_u32(const void* p) {
    u32 r;
    asm("{ .reg .u64 t; cvta.to.shared.u64 t, %1; cvt.u32.u64 %0, t; }" : "=r"(r) : "l"(p));
    return r;
}
__device__ __forceinline__ void mma_tf32(float* c, const u32* a, u32 b0, u32 b1) {
    asm volatile(
        "mma.sync.aligned.m16n8k8.row.col.f32.tf32.tf32.f32 "
        "{%0,%1,%2,%3}, {%4,%5,%6,%7}, {%8,%9}, {%0,%1,%2,%3};"
        : "+f"(c[0]), "+f"(c[1]), "+f"(c[2]), "+f"(c[3])
        : "r"(a[0]), "r"(a[1]), "r"(a[2]), "r"(a[3]), "r"(b0), "r"(b1));
}

__global__ void __launch_bounds__(256, 1) mhs_mma_kernel(
    const float* __restrict__ v,     // [B,H,S,E]
    const float* __restrict__ rel,   // [B,S,S,768]
    const float* __restrict__ W,     // [25,768] fp32
    const float* __restrict__ bias,  // [25]
    float* __restrict__ out)         // [B,S,25,S]
{
    extern __shared__ float smem[];
    const int tid  = threadIdx.x;
    const int w    = tid >> 5;           // warp 0..7, owns sq rows 32w..32w+31
    const int lane = tid & 31;
    const int g    = lane >> 2;          // groupID
    const int tg   = lane & 3;           // thread-in-group

    const int blk = blockIdx.x;
    const int b   = blk >> 8;
    const int sk  = blk & 255;

    float* p_s    = smem + OFF_PS;
    float* v_s    = smem + OFF_VS;
    float* cv_s   = smem + OFF_CVS;
    float* bias_s = smem + OFF_BIAS;
    float* rawb   = smem + OFF_RAW + w * (4 * RBUF);
    const u32 raw_su = smem_u32(rawb);
    const u32* ws = (const u32*)smem;    // tf32 W frags

    const float* relb = rel + (size_t)b * S_ * RS + (size_t)sk * D_;
    const float* myrel = relb + (size_t)(32 * w) * RS;

    // ---- prefetch chunks 0..2 ----
#pragma unroll
    for (int c = 0; c < 3; ++c) {
#pragma unroll
        for (int i = 0; i < 4; ++i) {
            int r = g + 8 * i;
            cpasync16(raw_su + (u32)((c * RBUF + r * RSTRIDE) * 4 + tg * 16),
                      myrel + (size_t)r * RS + 16 * c + tg * 4);
        }
        cp_commit();
    }

    // ---- stage p_s, v_s, bias ----
    for (int i = tid; i < H_ * S_; i += 256) {
        int h = i >> 8, sq = i & 255;
        p_s[i] = g_pt[(((size_t)b * H_ + h) * S_ + sk) * S_ + sq];
    }
    for (int i = tid; i < D_; i += 256) {
        int h = i >> 6, e = i & 63;
        v_s[i] = v[(((size_t)b * H_ + h) * S_ + sk) * E_ + e];
    }
    if (tid < L_) bias_s[tid] = bias[tid];

    // ---- stage packed W (96KB from L2) ----
    {
        const uint4* src = (const uint4*)g_wp;
        uint4* dst = (uint4*)smem;
        for (int i = tid; i < WPN / 4; i += 256) dst[i] = src[i];
    }
    __syncthreads();

    // ---- cv[l][h] = sum_e W[l, 64h+e] * v[h,e] ----
    for (int task = tid; task < L_ * H_; task += 256) {
        int l = task / H_, h = task - l * H_;
        const float4* wr = (const float4*)(W + l * D_ + h * 64);
        const float4* vr = (const float4*)(v_s + h * 64);
        float s = 0.f;
#pragma unroll
        for (int e = 0; e < 16; ++e) {
            float4 a = wr[e], c = vr[e];
            s += a.x * c.x + a.y * c.y + a.z * c.z + a.w * c.w;
        }
        cv_s[task] = s;
    }
    __syncthreads();

    // ---- accumulators ----
    float acc[2][4][4];
#pragma unroll
    for (int m = 0; m < 2; ++m)
#pragma unroll
        for (int nt = 0; nt < 4; ++nt)
#pragma unroll
            for (int q = 0; q < 4; ++q) acc[m][nt][q] = 0.f;

    float pv[4] = {0.f, 0.f, 0.f, 0.f};
    const float* pbase = p_s + 32 * w;

#pragma unroll 1
    for (int c = 0; c < NCHUNK; c += 4) {
#pragma unroll
        for (int u = 0; u < 4; ++u) {
            const int cc = c + u;

            // issue cp.async for chunk cc+3 into buf (u+3)&3
            if (cc + 3 < NCHUNK) {
                const int c3 = cc + 3;
                const u32 du = raw_su + (u32)(((u + 3) & 3) * RBUF * 4);
#pragma unroll
                for (int i = 0; i < 4; ++i) {
                    int r = g + 8 * i;
                    cpasync16(du + (u32)(r * RSTRIDE * 4 + tg * 16),
                              myrel + (size_t)r * RS + 16 * c3 + tg * 4);
                }
            }
            cp_commit();
            cp_wait3();     // chunk cc resident

            if ((cc & 3) == 0) {
                const float* pb = pbase + (cc >> 2) * 256;
                pv[0] = pb[g];
                pv[1] = pb[g + 8];
                pv[2] = pb[g + 16];
                pv[3] = pb[g + 24];
            }

            // convert: a[m][s][4] tf32 fragments (y = pv * rel)
            u32 a[2][2][4];
            {
                const float* rp = rawb + u * RBUF;
#pragma unroll
                for (int m = 0; m < 2; ++m) {
                    const float pA = pv[2 * m];
                    const float pB = pv[2 * m + 1];
                    const float* q0 = rp + (16 * m + g) * RSTRIDE + tg;
                    const float* q1 = rp + (16 * m + g + 8) * RSTRIDE + tg;
#pragma unroll
                    for (int s = 0; s < 2; ++s) {
                        a[m][s][0] = f2tf32(q0[8 * s] * pA);
                        a[m][s][1] = f2tf32(q1[8 * s] * pB);
                        a[m][s][2] = f2tf32(q0[8 * s + 4] * pA);
                        a[m][s][3] = f2tf32(q1[8 * s + 4] * pB);
                    }
                }
            }

            // MMAs: 4 ntiles x 2 ksteps x 2 mtiles = 16
#pragma unroll
            for (int nt = 0; nt < 4; ++nt) {
#pragma unroll
                for (int s = 0; s < 2; ++s) {
                    const int bi = (((2 * cc + s) * 32) + nt * 8 + g) * 8 + tg * 2;
                    u64 bp = *(const u64*)(ws + bi);
                    u32 b0 = (u32)bp, b1 = (u32)(bp >> 32);
                    mma_tf32(acc[0][nt], a[0][s], b0, b1);
                    mma_tf32(acc[1][nt], a[1][s], b0, b1);
                }
            }
        }
    }

    // ---- epilogue: bias + v-correction + store ----
    float* ob = out + ((size_t)(b * S_ + sk) * L_) * S_;
#pragma unroll
    for (int m = 0; m < 2; ++m) {
#pragma unroll
        for (int i = 0; i < 2; ++i) {
            const int row = 32 * w + 16 * m + g + 8 * i;
            float pr[H_];
#pragma unroll
            for (int h = 0; h < H_; ++h) pr[h] = p_s[h * 256 + row];
#pragma unroll
            for (int nt = 0; nt < 4; ++nt) {
#pragma unroll
                for (int j = 0; j < 2; ++j) {
                    const int l = 8 * nt + 2 * tg + j;
                    if (l < L_) {
                        float val = acc[m][nt][2 * i + j] + bias_s[l];
#pragma unroll
                        for (int h = 0; h < H_; ++h)
                            val += pr[h] * cv_s[l * H_ + h];
                        ob[(size_t)l * S_ + row] = val;
                    }
                }
            }
        }
    }
}

extern "C" void kernel_launch(void* const* d_in, const int* in_sizes, int n_in,
                              void* d_out, int out_size) {
    const float* p    = (const float*)d_in[0];
    const float* v    = (const float*)d_in[1];
    const float* rel  = (const float*)d_in[2];
    const float* W    = (const float*)d_in[3];
    const float* bias = (const float*)d_in[4];
    float* out = (float*)d_out;

    dim3 gt(S_ / 32, S_ / 32, B_ * H_ + 1);
    prep_kernel<<<gt, dim3(32, 8)>>>(p, W);

    const int smem_bytes = SMEM_FLOATS * (int)sizeof(float);  // 229680
    cudaFuncSetAttribute(mhs_mma_kernel,
                         cudaFuncAttributeMaxDynamicSharedMemorySize, smem_bytes);
    mhs_mma_kernel<<<B_ * S_, 256, smem_bytes>>>(v, rel, W, bias, out);
}

// round 8
// speedup vs baseline: 1.1248x; 1.0330x over previous
#include <cuda_runtime.h>
#include <cuda_bf16.h>
#include <cstdint>

#define B_ 2
#define H_ 12
#define S_ 256
#define E_ 64
#define D_ 768
#define L_ 25
#define RS (S_ * D_)      // rel sq-stride (floats)
#define NCHUNK 48         // k16 chunks
#define RSTRIDE 28        // raw tile row stride (floats)
#define WROWS 16          // sq rows per warp
#define RBUF (WROWS * RSTRIDE)   // floats per raw buffer (448)
#define TPB 512
#define NW 16             // warps per block

typedef unsigned long long u64;
typedef unsigned int u32;

// ---- smem layout (float offsets) ----
#define OFF_WS   0         // W tf32 frags: 96 ksteps x 32 n x 8 = 24576 u32
#define OFF_RAW  24576     // 16 warps x 4 bufs x 448 = 28672
#define OFF_PS   53248     // 12 x 256
#define OFF_VS   56320     // 768
#define OFF_CVS  57088     // 300
#define OFF_BIAS 57388     // 32
#define SMEM_FLOATS 57420  // 229680 bytes

#define WPN 24576          // u32 in W frag region

__device__ float g_pt[B_ * H_ * S_ * S_];
__device__ u32   g_wp[WPN];

__device__ __forceinline__ u32 f2tf32(float x) {
    u32 r;
    asm("cvt.rna.tf32.f32 %0, %1;" : "=r"(r) : "f"(x));
    return r;
}

// z<24: transpose p; z==24: pack W into tf32 mma B-fragment layout
__global__ void prep_kernel(const float* __restrict__ p, const float* __restrict__ W) {
    if (blockIdx.z == 24) {
        int flat = blockIdx.y * 8 + blockIdx.x;      // 0..63
        if (flat >= 48) return;
        int t = flat * 256 + threadIdx.y * 32 + threadIdx.x;  // 0..12287
        int S = t >> 7;            // kstep 0..95
        int r = t & 127;
        int n = r >> 2, tg = r & 3;
#pragma unroll
        for (int j = 0; j < 2; ++j) {
            int k = 8 * S + tg + 4 * j;
            float wv = (n < L_) ? W[n * D_ + k] : 0.0f;
            g_wp[(S * 32 + n) * 8 + tg * 2 + j] = f2tf32(wv);
        }
        return;
    }
    __shared__ float tile[32][33];
    int bh = blockIdx.z, x0 = blockIdx.x * 32, y0 = blockIdx.y * 32;
    int tx = threadIdx.x, ty = threadIdx.y;
    const float* src = p + (size_t)bh * (S_ * S_);
#pragma unroll
    for (int j = 0; j < 32; j += 8)
        tile[ty + j][tx] = src[(size_t)(y0 + ty + j) * S_ + (x0 + tx)];
    __syncthreads();
    float* dst = g_pt + (size_t)bh * (S_ * S_);
#pragma unroll
    for (int j = 0; j < 32; j += 8)
        dst[(size_t)(x0 + ty + j) * S_ + (y0 + tx)] = tile[tx][ty + j];
}

__device__ __forceinline__ void cpasync16(u32 dst, const float* src) {
    asm volatile("cp.async.cg.shared.global [%0], [%1], 16;\n" :: "r"(dst), "l"(src));
}
__device__ __forceinline__ void cp_commit() {
    asm volatile("cp.async.commit_group;\n" ::: "memory");
}
__device__ __forceinline__ void cp_wait3() {
    asm volatile("cp.async.wait_group 3;\n" ::: "memory");
}
__device__ __forceinline__ u32 smem_u32(const void* p) {
    u32 r;
    asm("{ .reg .u64 t; cvta.to.shared.u64 t, %1; cvt.u32.u64 %0, t; }" : "=r"(r) : "l"(p));
    return r;
}
__device__ __forceinline__ void mma_tf32(float* c, const u32* a, u32 b0, u32 b1) {
    asm volatile(
        "mma.sync.aligned.m16n8k8.row.col.f32.tf32.tf32.f32 "
        "{%0,%1,%2,%3}, {%4,%5,%6,%7}, {%8,%9}, {%0,%1,%2,%3};"
        : "+f"(c[0]), "+f"(c[1]), "+f"(c[2]), "+f"(c[3])
        : "r"(a[0]), "r"(a[1]), "r"(a[2]), "r"(a[3]), "r"(b0), "r"(b1));
}

__global__ void __launch_bounds__(TPB, 1) mhs_mma_kernel(
    const float* __restrict__ v,     // [B,H,S,E]
    const float* __restrict__ rel,   // [B,S,S,768]
    const float* __restrict__ W,     // [25,768] fp32
    const float* __restrict__ bias,  // [25]
    float* __restrict__ out)         // [B,S,25,S]
{
    extern __shared__ float smem[];
    const int tid  = threadIdx.x;
    const int w    = tid >> 5;           // warp 0..15, owns sq rows 16w..16w+15
    const int lane = tid & 31;
    const int g    = lane >> 2;          // groupID
    const int tg   = lane & 3;           // thread-in-group

    const int blk = blockIdx.x;
    const int b   = blk >> 8;
    const int sk  = blk & 255;

    float* p_s    = smem + OFF_PS;
    float* v_s    = smem + OFF_VS;
    float* cv_s   = smem + OFF_CVS;
    float* bias_s = smem + OFF_BIAS;
    float* rawb   = smem + OFF_RAW + w * (4 * RBUF);
    const u32 raw_su = smem_u32(rawb);
    const u32* ws = (const u32*)smem;    // tf32 W frags

    const float* relb = rel + (size_t)b * S_ * RS + (size_t)sk * D_;
    const float* myrel = relb + (size_t)(WROWS * w) * RS;

    // ---- prefetch chunks 0..2 (2 cp.async.16 per lane per chunk) ----
#pragma unroll
    for (int c = 0; c < 3; ++c) {
#pragma unroll
        for (int i = 0; i < 2; ++i) {
            int r = g + 8 * i;
            cpasync16(raw_su + (u32)((c * RBUF + r * RSTRIDE) * 4 + tg * 16),
                      myrel + (size_t)r * RS + 16 * c + tg * 4);
        }
        cp_commit();
    }

    // ---- stage p_s, v_s, bias ----
    for (int i = tid; i < H_ * S_; i += TPB) {
        int h = i >> 8, sq = i & 255;
        p_s[i] = g_pt[(((size_t)b * H_ + h) * S_ + sk) * S_ + sq];
    }
    for (int i = tid; i < D_; i += TPB) {
        int h = i >> 6, e = i & 63;
        v_s[i] = v[(((size_t)b * H_ + h) * S_ + sk) * E_ + e];
    }
    if (tid < L_) bias_s[tid] = bias[tid];

    // ---- stage packed W (96KB from L2) ----
    {
        const uint4* src = (const uint4*)g_wp;
        uint4* dst = (uint4*)smem;
        for (int i = tid; i < WPN / 4; i += TPB) dst[i] = src[i];
    }
    __syncthreads();

    // ---- cv[l][h] = sum_e W[l, 64h+e] * v[h,e] ----
    for (int task = tid; task < L_ * H_; task += TPB) {
        int l = task / H_, h = task - l * H_;
        const float4* wr = (const float4*)(W + l * D_ + h * 64);
        const float4* vr = (const float4*)(v_s + h * 64);
        float s = 0.f;
#pragma unroll
        for (int e = 0; e < 16; ++e) {
            float4 a = wr[e], c = vr[e];
            s += a.x * c.x + a.y * c.y + a.z * c.z + a.w * c.w;
        }
        cv_s[task] = s;
    }
    __syncthreads();

    // ---- accumulators: 4 ntiles x 4 (one m16 tile per warp) ----
    float acc[4][4];
#pragma unroll
    for (int nt = 0; nt < 4; ++nt)
#pragma unroll
        for (int q = 0; q < 4; ++q) acc[nt][q] = 0.f;

    float pvA = 0.f, pvB = 0.f;
    const float* pbase = p_s + WROWS * w;

#pragma unroll 1
    for (int c = 0; c < NCHUNK; c += 4) {
#pragma unroll
        for (int u = 0; u < 4; ++u) {
            const int cc = c + u;

            // issue cp.async for chunk cc+3 into buf (u+3)&3
            if (cc + 3 < NCHUNK) {
                const int c3 = cc + 3;
                const u32 du = raw_su + (u32)(((u + 3) & 3) * RBUF * 4);
#pragma unroll
                for (int i = 0; i < 2; ++i) {
                    int r = g + 8 * i;
                    cpasync16(du + (u32)(r * RSTRIDE * 4 + tg * 16),
                              myrel + (size_t)r * RS + 16 * c3 + tg * 4);
                }
            }
            cp_commit();
            cp_wait3();     // chunk cc resident

            if ((cc & 3) == 0) {
                const float* pb = pbase + (cc >> 2) * 256;
                pvA = pb[g];
                pvB = pb[g + 8];
            }

            // convert: a[s][4] tf32 fragments (y = pv * rel)
            u32 a[2][4];
            {
                const float* rp = rawb + u * RBUF;
                const float* q0 = rp + g * RSTRIDE + tg;
                const float* q1 = rp + (g + 8) * RSTRIDE + tg;
#pragma unroll
                for (int s = 0; s < 2; ++s) {
                    a[s][0] = f2tf32(q0[8 * s] * pvA);
                    a[s][1] = f2tf32(q1[8 * s] * pvB);
                    a[s][2] = f2tf32(q0[8 * s + 4] * pvA);
                    a[s][3] = f2tf32(q1[8 * s + 4] * pvB);
                }
            }

            // MMAs: 4 ntiles x 2 ksteps
#pragma unroll
            for (int nt = 0; nt < 4; ++nt) {
#pragma unroll
                for (int s = 0; s < 2; ++s) {
                    const int bi = (((2 * cc + s) * 32) + nt * 8 + g) * 8 + tg * 2;
                    u64 bp = *(const u64*)(ws + bi);
                    u32 b0 = (u32)bp, b1 = (u32)(bp >> 32);
                    mma_tf32(acc[nt], a[s], b0, b1);
                }
            }
        }
    }

    // ---- epilogue: bias + v-correction + store ----
    float* ob = out + ((size_t)(b * S_ + sk) * L_) * S_;
#pragma unroll
    for (int i = 0; i < 2; ++i) {
        const int row = WROWS * w + g + 8 * i;
        float pr[H_];
#pragma unroll
        for (int h = 0; h < H_; ++h) pr[h] = p_s[h * 256 + row];
#pragma unroll
        for (int nt = 0; nt < 4; ++nt) {
#pragma unroll
            for (int j = 0; j < 2; ++j) {
                const int l = 8 * nt + 2 * tg + j;
                if (l < L_) {
                    float val = acc[nt][2 * i + j] + bias_s[l];
#pragma unroll
                    for (int h = 0; h < H_; ++h)
                        val += pr[h] * cv_s[l * H_ + h];
                    ob[(size_t)l * S_ + row] = val;
                }
            }
        }
    }
}

extern "C" void kernel_launch(void* const* d_in, const int* in_sizes, int n_in,
                              void* d_out, int out_size) {
    const float* p    = (const float*)d_in[0];
    const float* v    = (const float*)d_in[1];
    const float* rel  = (const float*)d_in[2];
    const float* W    = (const float*)d_in[3];
    const float* bias = (const float*)d_in[4];
    float* out = (float*)d_out;

    dim3 gt(S_ / 32, S_ / 32, B_ * H_ + 1);
    prep_kernel<<<gt, dim3(32, 8)>>>(p, W);

    const int smem_bytes = SMEM_FLOATS * (int)sizeof(float);  // 229680
    cudaFuncSetAttribute(mhs_mma_kernel,
                         cudaFuncAttributeMaxDynamicSharedMemorySize, smem_bytes);
    mhs_mma_kernel<<<B_ * S_, TPB, smem_bytes>>>(v, rel, W, bias, out);
}

// round 9
// speedup vs baseline: 1.1535x; 1.0255x over previous
#include <cuda_runtime.h>
#include <cuda_bf16.h>
#include <cstdint>

#define B_ 2
#define H_ 12
#define S_ 256
#define E_ 64
#define D_ 768
#define L_ 25
#define RS (S_ * D_)      // rel sq-stride (floats)
#define NCHUNK 48         // k16 chunks
#define RSTRIDE 28        // raw tile row stride (floats)
#define WROWS 16          // sq rows per warp
#define RBUF (WROWS * RSTRIDE)   // floats per raw buffer (448)
#define NBUF 5
#define TPB 512
#define NPAD 26           // W frag n-dim padding

typedef unsigned long long u64;
typedef unsigned int u32;

// ---- smem layout (float offsets) ----
#define OFF_WS   0                      // 96 ksteps x 26 n x 8 = 19968 u32
#define OFF_RAW  19968                  // 16 warps x 5 bufs x 448 = 35840
#define OFF_VS   55808                  // 768
#define OFF_CVS  56576                  // 300
#define OFF_BIAS 56876                  // 32
#define SMEM_FLOATS 56912               // 227648 bytes

#define WPN 19968          // u32 in W frag region

__device__ float g_pt[B_ * H_ * S_ * S_];
__device__ u32   g_wp[WPN];

__device__ __forceinline__ u32 f2tf32(float x) {
    u32 r;
    asm("cvt.rna.tf32.f32 %0, %1;" : "=r"(r) : "f"(x));
    return r;
}

// z<24: transpose p; z==24: pack W into tf32 mma B-fragment layout (n padded to 26)
__global__ void prep_kernel(const float* __restrict__ p, const float* __restrict__ W) {
    if (blockIdx.z == 24) {
        int flat = blockIdx.y * 8 + blockIdx.x;      // 0..63
        int t = flat * 256 + threadIdx.y * 32 + threadIdx.x;
        if (t >= 96 * NPAD * 4) return;
        int S = t / (NPAD * 4);
        int r = t - S * (NPAD * 4);
        int n = r >> 2, tg = r & 3;
#pragma unroll
        for (int j = 0; j < 2; ++j) {
            int k = 8 * S + tg + 4 * j;
            float wv = (n < L_) ? W[n * D_ + k] : 0.0f;
            g_wp[(S * NPAD + n) * 8 + tg * 2 + j] = f2tf32(wv);
        }
        return;
    }
    __shared__ float tile[32][33];
    int bh = blockIdx.z, x0 = blockIdx.x * 32, y0 = blockIdx.y * 32;
    int tx = threadIdx.x, ty = threadIdx.y;
    const float* src = p + (size_t)bh * (S_ * S_);
#pragma unroll
    for (int j = 0; j < 32; j += 8)
        tile[ty + j][tx] = src[(size_t)(y0 + ty + j) * S_ + (x0 + tx)];
    __syncthreads();
    float* dst = g_pt + (size_t)bh * (S_ * S_);
#pragma unroll
    for (int j = 0; j < 32; j += 8)
        dst[(size_t)(x0 + ty + j) * S_ + (y0 + tx)] = tile[tx][ty + j];
}

__device__ __forceinline__ void cpasync16(u32 dst, const float* src) {
    asm volatile("cp.async.cg.shared.global [%0], [%1], 16;\n" :: "r"(dst), "l"(src));
}
__device__ __forceinline__ void cp_commit() {
    asm volatile("cp.async.commit_group;\n" ::: "memory");
}
__device__ __forceinline__ void cp_wait4() {
    asm volatile("cp.async.wait_group 4;\n" ::: "memory");
}
__device__ __forceinline__ u32 smem_u32(const void* p) {
    u32 r;
    asm("{ .reg .u64 t; cvta.to.shared.u64 t, %1; cvt.u32.u64 %0, t; }" : "=r"(r) : "l"(p));
    return r;
}
__device__ __forceinline__ void mma_tf32(float* c, const u32* a, u32 b0, u32 b1) {
    asm volatile(
        "mma.sync.aligned.m16n8k8.row.col.f32.tf32.tf32.f32 "
        "{%0,%1,%2,%3}, {%4,%5,%6,%7}, {%8,%9}, {%0,%1,%2,%3};"
        : "+f"(c[0]), "+f"(c[1]), "+f"(c[2]), "+f"(c[3])
        : "r"(a[0]), "r"(a[1]), "r"(a[2]), "r"(a[3]), "r"(b0), "r"(b1));
}

__global__ void __launch_bounds__(TPB, 1) mhs_mma_kernel(
    const float* __restrict__ v,     // [B,H,S,E]
    const float* __restrict__ rel,   // [B,S,S,768]
    const float* __restrict__ W,     // [25,768] fp32
    const float* __restrict__ bias,  // [25]
    float* __restrict__ out)         // [B,S,25,S]
{
    extern __shared__ float smem[];
    const int tid  = threadIdx.x;
    const int w    = tid >> 5;           // warp 0..15, owns sq rows 16w..16w+15
    const int lane = tid & 31;
    const int g    = lane >> 2;          // groupID
    const int tg   = lane & 3;           // thread-in-group

    const int blk = blockIdx.x;
    const int b   = blk >> 8;
    const int sk  = blk & 255;

    float* v_s    = smem + OFF_VS;
    float* cv_s   = smem + OFF_CVS;
    float* bias_s = smem + OFF_BIAS;
    float* rawb   = smem + OFF_RAW + w * (NBUF * RBUF);
    const u32 raw_su = smem_u32(rawb);
    const u32* ws = (const u32*)smem;    // tf32 W frags

    const float* relb = rel + (size_t)b * S_ * RS + (size_t)sk * D_;
    const float* myrel = relb + (size_t)(WROWS * w) * RS;

    // per-lane clamped n for W frag reads (row 25 is zeros)
    int n_eff[4];
#pragma unroll
    for (int nt = 0; nt < 4; ++nt) {
        int n = nt * 8 + g;
        n_eff[nt] = (n > 25) ? 25 : n;
    }

    // ---- prefetch chunks 0..3 into bufs 0..3 ----
#pragma unroll
    for (int c = 0; c < 4; ++c) {
#pragma unroll
        for (int i = 0; i < 2; ++i) {
            int r = g + 8 * i;
            cpasync16(raw_su + (u32)((c * RBUF + r * RSTRIDE) * 4 + tg * 16),
                      myrel + (size_t)r * RS + 16 * c + tg * 4);
        }
        cp_commit();
    }

    // ---- stage v_s, bias ----
    for (int i = tid; i < D_; i += TPB) {
        int h = i >> 6, e = i & 63;
        v_s[i] = v[(((size_t)b * H_ + h) * S_ + sk) * E_ + e];
    }
    if (tid < L_) bias_s[tid] = bias[tid];

    // ---- stage packed W (80KB from L2) ----
    {
        const uint4* src = (const uint4*)g_wp;
        uint4* dst = (uint4*)smem;
        for (int i = tid; i < WPN / 4; i += TPB) dst[i] = src[i];
    }
    __syncthreads();

    // ---- cv[l][h] = sum_e W[l, 64h+e] * v[h,e] ----
    for (int task = tid; task < L_ * H_; task += TPB) {
        int l = task / H_, h = task - l * H_;
        const float4* wr = (const float4*)(W + l * D_ + h * 64);
        const float4* vr = (const float4*)(v_s + h * 64);
        float s = 0.f;
#pragma unroll
        for (int e = 0; e < 16; ++e) {
            float4 a = wr[e], c = vr[e];
            s += a.x * c.x + a.y * c.y + a.z * c.z + a.w * c.w;
        }
        cv_s[task] = s;
    }
    __syncthreads();

    // ---- accumulators ----
    float acc[4][4];
#pragma unroll
    for (int nt = 0; nt < 4; ++nt)
#pragma unroll
        for (int q = 0; q < 4; ++q) acc[nt][q] = 0.f;

    // pv register pipeline (p values from L2-hot g_pt)
    const float* ptb = g_pt + (((size_t)b * H_) * S_ + sk) * S_ + WROWS * w;
    float pvA = __ldg(ptb + g);
    float pvB = __ldg(ptb + g + 8);
    float pvAn = 0.f, pvBn = 0.f;

    int bufc = 0;

#pragma unroll 1
    for (int cc = 0; cc < NCHUNK; ++cc) {
        // prefetch chunk cc+4 into buffer (bufc+4)%5
        if (cc + 4 < NCHUNK) {
            int bufp = bufc + 4; if (bufp >= NBUF) bufp -= NBUF;
            const u32 du = raw_su + (u32)(bufp * RBUF * 4);
#pragma unroll
            for (int i = 0; i < 2; ++i) {
                int r = g + 8 * i;
                cpasync16(du + (u32)(r * RSTRIDE * 4 + tg * 16),
                          myrel + (size_t)r * RS + 16 * (cc + 4) + tg * 4);
            }
        }
        cp_commit();
        cp_wait4();     // chunk cc resident

        // prefetch next-h pv two chunks before use
        if ((cc & 3) == 1) {
            const int hn = (cc >> 2) + 1;
            if (hn < H_) {
                pvAn = __ldg(ptb + (size_t)hn * (S_ * S_) + g);
                pvBn = __ldg(ptb + (size_t)hn * (S_ * S_) + g + 8);
            }
        }

        // convert: a[s][4] tf32 fragments (y = pv * rel)
        u32 a[2][4];
        {
            const float* rp = rawb + bufc * RBUF;
            const float* q0 = rp + g * RSTRIDE + tg;
            const float* q1 = rp + (g + 8) * RSTRIDE + tg;
#pragma unroll
            for (int s = 0; s < 2; ++s) {
                a[s][0] = f2tf32(q0[8 * s] * pvA);
                a[s][1] = f2tf32(q1[8 * s] * pvB);
                a[s][2] = f2tf32(q0[8 * s + 4] * pvA);
                a[s][3] = f2tf32(q1[8 * s + 4] * pvB);
            }
        }

        // MMAs: 4 ntiles x 2 ksteps
#pragma unroll
        for (int nt = 0; nt < 4; ++nt) {
#pragma unroll
            for (int s = 0; s < 2; ++s) {
                const int bi = ((2 * cc + s) * NPAD + n_eff[nt]) * 8 + tg * 2;
                u64 bp = *(const u64*)(ws + bi);
                u32 b0 = (u32)bp, b1 = (u32)(bp >> 32);
                mma_tf32(acc[nt], a[s], b0, b1);
            }
        }

        bufc = bufc + 1; if (bufc >= NBUF) bufc -= NBUF;
        if ((cc & 3) == 3) { pvA = pvAn; pvB = pvBn; }
    }

    // ---- epilogue: bias + v-correction + store ----
    const float* pte = g_pt + (((size_t)b * H_) * S_ + sk) * S_;
    float* ob = out + ((size_t)(b * S_ + sk) * L_) * S_;
#pragma unroll
    for (int i = 0; i < 2; ++i) {
        const int row = WROWS * w + g + 8 * i;
        float pr[H_];
#pragma unroll
        for (int h = 0; h < H_; ++h)
            pr[h] = __ldg(pte + (size_t)h * (S_ * S_) + row);
#pragma unroll
        for (int nt = 0; nt < 4; ++nt) {
#pragma unroll
            for (int j = 0; j < 2; ++j) {
                const int l = 8 * nt + 2 * tg + j;
                if (l < L_) {
                    float val = acc[nt][2 * i + j] + bias_s[l];
#pragma unroll
                    for (int h = 0; h < H_; ++h)
                        val += pr[h] * cv_s[l * H_ + h];
                    ob[(size_t)l * S_ + row] = val;
                }
            }
        }
    }
}

extern "C" void kernel_launch(void* const* d_in, const int* in_sizes, int n_in,
                              void* d_out, int out_size) {
    const float* p    = (const float*)d_in[0];
    const float* v    = (const float*)d_in[1];
    const float* rel  = (const float*)d_in[2];
    const float* W    = (const float*)d_in[3];
    const float* bias = (const float*)d_in[4];
    float* out = (float*)d_out;

    dim3 gt(S_ / 32, S_ / 32, B_ * H_ + 1);
    prep_kernel<<<gt, dim3(32, 8)>>>(p, W);

    const int smem_bytes = SMEM_FLOATS * (int)sizeof(float);  // 227648
    cudaFuncSetAttribute(mhs_mma_kernel,
                         cudaFuncAttributeMaxDynamicSharedMemorySize, smem_bytes);
    mhs_mma_kernel<<<B_ * S_, TPB, smem_bytes>>>(v, rel, W, bias, out);
}

// round 10
// speedup vs baseline: 1.1554x; 1.0016x over previous
#include <cuda_runtime.h>
#include <cuda_bf16.h>
#include <cstdint>

#define B_ 2
#define H_ 12
#define S_ 256
#define E_ 64
#define D_ 768
#define L_ 25
#define RS (S_ * D_)      // rel sq-stride (floats)
#define NCHUNK 48         // k16 chunks
#define RSTRIDE 20        // raw tile row stride (floats), conflict-free
#define WROWS 16          // sq rows per warp
#define RBUF (WROWS * RSTRIDE)   // floats per raw buffer (320)
#define NBUF 6
#define TPB 512
#define NPAD 26           // W frag n-dim padding
#define WCHUNK (2 * NPAD * 8)    // u32 per chunk in W frag region (416)

typedef unsigned long long u64;
typedef unsigned int u32;

// ---- smem layout (float offsets) ----
#define OFF_WS   0                      // 96 ksteps x 26 n x 8 = 19968 u32
#define OFF_RAW  19968                  // 16 warps x 6 bufs x 320 = 30720
#define OFF_VS   50688                  // 768
#define OFF_CVS  51456                  // 300
#define OFF_BIAS 51756                  // 32
#define SMEM_FLOATS 51788               // 207152 bytes

#define WPN 19968          // u32 in W frag region

__device__ float g_pt[B_ * H_ * S_ * S_];
__device__ u32   g_wp[WPN];

__device__ __forceinline__ u32 f2tf32(float x) {
    u32 r;
    asm("cvt.rna.tf32.f32 %0, %1;" : "=r"(r) : "f"(x));
    return r;
}

// z<24: transpose p; z==24: pack W into tf32 mma B-fragment layout (n padded to 26)
__global__ void prep_kernel(const float* __restrict__ p, const float* __restrict__ W) {
    if (blockIdx.z == 24) {
        int flat = blockIdx.y * 8 + blockIdx.x;      // 0..63
        int t = flat * 256 + threadIdx.y * 32 + threadIdx.x;
        if (t >= 96 * NPAD * 4) return;
        int S = t / (NPAD * 4);
        int r = t - S * (NPAD * 4);
        int n = r >> 2, tg = r & 3;
#pragma unroll
        for (int j = 0; j < 2; ++j) {
            int k = 8 * S + tg + 4 * j;
            float wv = (n < L_) ? W[n * D_ + k] : 0.0f;
            g_wp[(S * NPAD + n) * 8 + tg * 2 + j] = f2tf32(wv);
        }
        return;
    }
    __shared__ float tile[32][33];
    int bh = blockIdx.z, x0 = blockIdx.x * 32, y0 = blockIdx.y * 32;
    int tx = threadIdx.x, ty = threadIdx.y;
    const float* src = p + (size_t)bh * (S_ * S_);
#pragma unroll
    for (int j = 0; j < 32; j += 8)
        tile[ty + j][tx] = src[(size_t)(y0 + ty + j) * S_ + (x0 + tx)];
    __syncthreads();
    float* dst = g_pt + (size_t)bh * (S_ * S_);
#pragma unroll
    for (int j = 0; j < 32; j += 8)
        dst[(size_t)(x0 + ty + j) * S_ + (y0 + tx)] = tile[tx][ty + j];
}

__device__ __forceinline__ void cpasync16(u32 dst, const float* src) {
    asm volatile("cp.async.cg.shared.global [%0], [%1], 16;\n" :: "r"(dst), "l"(src));
}
__device__ __forceinline__ void cp_commit() {
    asm volatile("cp.async.commit_group;\n" ::: "memory");
}
__device__ __forceinline__ void cp_wait5() {
    asm volatile("cp.async.wait_group 5;\n" ::: "memory");
}
__device__ __forceinline__ u32 smem_u32(const void* p) {
    u32 r;
    asm("{ .reg .u64 t; cvta.to.shared.u64 t, %1; cvt.u32.u64 %0, t; }" : "=r"(r) : "l"(p));
    return r;
}
__device__ __forceinline__ void mma_tf32(float* c, const u32* a, u32 b0, u32 b1) {
    asm volatile(
        "mma.sync.aligned.m16n8k8.row.col.f32.tf32.tf32.f32 "
        "{%0,%1,%2,%3}, {%4,%5,%6,%7}, {%8,%9}, {%0,%1,%2,%3};"
        : "+f"(c[0]), "+f"(c[1]), "+f"(c[2]), "+f"(c[3])
        : "r"(a[0]), "r"(a[1]), "r"(a[2]), "r"(a[3]), "r"(b0), "r"(b1));
}

__global__ void __launch_bounds__(TPB, 1) mhs_mma_kernel(
    const float* __restrict__ v,     // [B,H,S,E]
    const float* __restrict__ rel,   // [B,S,S,768]
    const float* __restrict__ W,     // [25,768] fp32
    const float* __restrict__ bias,  // [25]
    float* __restrict__ out)         // [B,S,25,S]
{
    extern __shared__ float smem[];
    const int tid  = threadIdx.x;
    const int w    = tid >> 5;           // warp 0..15, owns sq rows 16w..16w+15
    const int lane = tid & 31;
    const int g    = lane >> 2;          // groupID
    const int tg   = lane & 3;           // thread-in-group

    const int blk = blockIdx.x;
    const int b   = blk >> 8;
    const int sk  = blk & 255;

    float* v_s    = smem + OFF_VS;
    float* cv_s   = smem + OFF_CVS;
    float* bias_s = smem + OFF_BIAS;
    float* rawb   = smem + OFF_RAW + w * (NBUF * RBUF);
    const u32 raw_su = smem_u32(rawb);
    const u32* ws = (const u32*)smem;    // tf32 W frags

    const float* relb = rel + (size_t)b * S_ * RS + (size_t)sk * D_;
    const float* myrel = relb + (size_t)(WROWS * w) * RS;

    // loop-invariant W frag offsets (n clamped: row 25 is zeros)
    int n_off[4];
#pragma unroll
    for (int nt = 0; nt < 4; ++nt) {
        int n = nt * 8 + g;
        if (n > 25) n = 25;
        n_off[nt] = n * 8 + tg * 2;
    }

    // per-lane cp.async lane bases
    const float* src0 = myrel + (size_t)g * RS + tg * 4;            // row g
    const float* src1 = myrel + (size_t)(g + 8) * RS + tg * 4;      // row g+8
    const u32 dst0 = raw_su + (u32)(g * RSTRIDE * 4 + tg * 16);
    const u32 dst1 = dst0 + (u32)(8 * RSTRIDE * 4);

    // ---- prefetch chunks 0..4 into bufs 0..4 ----
#pragma unroll
    for (int c = 0; c < 5; ++c) {
        cpasync16(dst0 + (u32)(c * RBUF * 4), src0 + 16 * c);
        cpasync16(dst1 + (u32)(c * RBUF * 4), src1 + 16 * c);
        cp_commit();
    }

    // ---- stage v_s, bias ----
    for (int i = tid; i < D_; i += TPB) {
        int h = i >> 6, e = i & 63;
        v_s[i] = v[(((size_t)b * H_ + h) * S_ + sk) * E_ + e];
    }
    if (tid < L_) bias_s[tid] = bias[tid];

    // ---- stage packed W (80KB from L2) ----
    {
        const uint4* src = (const uint4*)g_wp;
        uint4* dst = (uint4*)smem;
        for (int i = tid; i < WPN / 4; i += TPB) dst[i] = src[i];
    }
    __syncthreads();

    // ---- cv[l][h] = sum_e W[l, 64h+e] * v[h,e] ----
    for (int task = tid; task < L_ * H_; task += TPB) {
        int l = task / H_, h = task - l * H_;
        const float4* wr = (const float4*)(W + l * D_ + h * 64);
        const float4* vr = (const float4*)(v_s + h * 64);
        float s = 0.f;
#pragma unroll
        for (int e = 0; e < 16; ++e) {
            float4 a = wr[e], c = vr[e];
            s += a.x * c.x + a.y * c.y + a.z * c.z + a.w * c.w;
        }
        cv_s[task] = s;
    }
    __syncthreads();

    // ---- accumulators ----
    float acc[4][4];
#pragma unroll
    for (int nt = 0; nt < 4; ++nt)
#pragma unroll
        for (int q = 0; q < 4; ++q) acc[nt][q] = 0.f;

    // pv register pipeline (p values from L2-hot g_pt)
    const float* ptb = g_pt + (((size_t)b * H_) * S_ + sk) * S_ + WROWS * w;
    float pvA = __ldg(ptb + g);
    float pvB = __ldg(ptb + g + 8);
    float pvAn = pvA, pvBn = pvB;

    // mainloop: 4 outer iterations x 12 static chunks
#pragma unroll 1
    for (int c = 0; c < NCHUNK; c += 12) {
        const int hb = c >> 2;
        const u32* wbase = ws + c * WCHUNK;
        const float* sc0 = src0 + 16 * c;
        const float* sc1 = src1 + 16 * c;

#pragma unroll
        for (int u = 0; u < 12; ++u) {
            const int cc = c + u;

            // prefetch chunk cc+5 into buf (u+5)%6 (all static offsets)
            if (cc + 5 < NCHUNK) {
                const u32 doff = (u32)((((u + 5) % 6) * RBUF) * 4);
                cpasync16(dst0 + doff, sc0 + 16 * (u + 5));
                cpasync16(dst1 + doff, sc1 + 16 * (u + 5));
            }
            cp_commit();
            cp_wait5();     // chunk cc resident

            // pv prefetch for next h at static positions (3 chunks early)
            if (u == 1 || u == 5 || u == 9) {
                int hn = hb + (u + 3) / 4;
                if (hn > H_ - 1) hn = H_ - 1;
                pvAn = __ldg(ptb + (size_t)hn * (S_ * S_) + g);
                pvBn = __ldg(ptb + (size_t)hn * (S_ * S_) + g + 8);
            }

            // convert: a[s][4] tf32 fragments (y = pv * rel), static buffer
            u32 a[2][4];
            {
                const float* rp = rawb + (u % 6) * RBUF;
                const float* q0 = rp + g * RSTRIDE + tg;
                const float* q1 = rp + (g + 8) * RSTRIDE + tg;
#pragma unroll
                for (int s = 0; s < 2; ++s) {
                    a[s][0] = f2tf32(q0[8 * s] * pvA);
                    a[s][1] = f2tf32(q1[8 * s] * pvB);
                    a[s][2] = f2tf32(q0[8 * s + 4] * pvA);
                    a[s][3] = f2tf32(q1[8 * s + 4] * pvB);
                }
            }

            // MMAs: 4 ntiles x 2 ksteps, W offsets static per u
#pragma unroll
            for (int nt = 0; nt < 4; ++nt) {
#pragma unroll
                for (int s = 0; s < 2; ++s) {
                    u64 bp = *(const u64*)(wbase + u * WCHUNK + s * (NPAD * 8) + n_off[nt]);
                    u32 b0 = (u32)bp, b1 = (u32)(bp >> 32);
                    mma_tf32(acc[nt], a[s], b0, b1);
                }
            }

            // h-boundary pv swap at static positions
            if (u == 3 || u == 7 || u == 11) { pvA = pvAn; pvB = pvBn; }
        }
    }

    // ---- epilogue: bias + v-correction + store ----
    const float* pte = g_pt + (((size_t)b * H_) * S_ + sk) * S_;
    float* ob = out + ((size_t)(b * S_ + sk) * L_) * S_;
#pragma unroll
    for (int i = 0; i < 2; ++i) {
        const int row = WROWS * w + g + 8 * i;
        float pr[H_];
#pragma unroll
        for (int h = 0; h < H_; ++h)
            pr[h] = __ldg(pte + (size_t)h * (S_ * S_) + row);
#pragma unroll
        for (int nt = 0; nt < 4; ++nt) {
#pragma unroll
            for (int j = 0; j < 2; ++j) {
                const int l = 8 * nt + 2 * tg + j;
                if (l < L_) {
                    float val = acc[nt][2 * i + j] + bias_s[l];
#pragma unroll
                    for (int h = 0; h < H_; ++h)
                        val += pr[h] * cv_s[l * H_ + h];
                    ob[(size_t)l * S_ + row] = val;
                }
            }
        }
    }
}

extern "C" void kernel_launch(void* const* d_in, const int* in_sizes, int n_in,
                              void* d_out, int out_size) {
    const float* p    = (const float*)d_in[0];
    const float* v    = (const float*)d_in[1];
    const float* rel  = (const float*)d_in[2];
    const float* W    = (const float*)d_in[3];
    const float* bias = (const float*)d_in[4];
    float* out = (float*)d_out;

    dim3 gt(S_ / 32, S_ / 32, B_ * H_ + 1);
    prep_kernel<<<gt, dim3(32, 8)>>>(p, W);

    const int smem_bytes = SMEM_FLOATS * (int)sizeof(float);  // 207152
    cudaFuncSetAttribute(mhs_mma_kernel,
                         cudaFuncAttributeMaxDynamicSharedMemorySize, smem_bytes);
    mhs_mma_kernel<<<B_ * S_, TPB, smem_bytes>>>(v, rel, W, bias, out);
}